// round 10
// baseline (speedup 1.0000x reference)
#include <cuda_runtime.h>
#include <cuda_fp16.h>
#include <cuda_fp8.h>
#include <math.h>
#include <stdint.h>

#define S_LEN 4096
#define B_DIM 32
#define H_DIM 512

#define CROSS_SCALE 4096.0f
#define INV_CROSS   2.44140625e-4f   // 2^-12

// ---------------- device scratch: W splits (transposed, [n][k]) ----------------
__device__ __half  g_Bh[H_DIM * H_DIM];    // fp16 hi(W[k][n])
__device__ uint8_t g_B8h[H_DIM * H_DIM];   // e4m3(W[k][n])
__device__ uint8_t g_B8l[H_DIM * H_DIM];   // e4m3((W - hi(W)) * 2^12)

__device__ __forceinline__ uint32_t smem_u32(const void* p) {
    uint32_t a;
    asm("{ .reg .u64 t; cvta.to.shared.u64 t, %1; cvt.u32.u64 %0, t; }" : "=r"(a) : "l"(p));
    return a;
}

#define LDSM4(r0, r1, r2, r3, addr) \
    asm volatile("ldmatrix.sync.aligned.m8n8.x4.shared.b16 {%0,%1,%2,%3}, [%4];" \
        : "=r"(r0), "=r"(r1), "=r"(r2), "=r"(r3) : "r"(addr))

#define MMA16816(c, a, b0, b1) \
    asm volatile("mma.sync.aligned.m16n8k16.row.col.f32.f16.f16.f32 " \
        "{%0,%1,%2,%3}, {%4,%5,%6,%7}, {%8,%9}, {%0,%1,%2,%3};" \
        : "+f"((c)[0]), "+f"((c)[1]), "+f"((c)[2]), "+f"((c)[3]) \
        : "r"((a)[0]), "r"((a)[1]), "r"((a)[2]), "r"((a)[3]), "r"(b0), "r"(b1))

#define MMA8(c, a, b0, b1) \
    asm volatile("mma.sync.aligned.m16n8k32.row.col.f32.e4m3.e4m3.f32 " \
        "{%0,%1,%2,%3}, {%4,%5,%6,%7}, {%8,%9}, {%0,%1,%2,%3};" \
        : "+f"((c)[0]), "+f"((c)[1]), "+f"((c)[2]), "+f"((c)[3]) \
        : "r"((a)[0]), "r"((a)[1]), "r"((a)[2]), "r"((a)[3]), "r"(b0), "r"(b1))

#define CP16(dst, src) \
    asm volatile("cp.async.cg.shared.global [%0], [%1], 16;" :: "r"(dst), "l"(src))
#define CP_COMMIT() asm volatile("cp.async.commit_group;" ::: "memory")
#define CP_WAIT0()  asm volatile("cp.async.wait_group 0;" ::: "memory")

// pack two f32 -> e4m3x2 (low byte = b operand)
__device__ __forceinline__ uint16_t cvt8x2(float hi, float lo) {
    uint16_t r;
    asm("cvt.rn.satfinite.e4m3x2.f32 %0, %1, %2;" : "=h"(r) : "f"(hi), "f"(lo));
    return r;
}

// ---------------- kernel 0: split W (transposed) ----------------
__global__ __launch_bounds__(256) void split_w(const float* __restrict__ Wm) {
    int idx = blockIdx.x * 256 + threadIdx.x;   // 0 .. 262143
    int k = idx >> 9, n = idx & 511;
    float v = Wm[idx];
    __half hi = __float2half_rn(v);
    float lof = v - __half2float(hi);
    g_Bh[n * H_DIM + k]  = hi;
    g_B8h[n * H_DIM + k] = __nv_fp8_e4m3(v).__x;
    g_B8l[n * H_DIM + k] = __nv_fp8_e4m3(lof * CROSS_SCALE).__x;
}

// ---------------- kernel 1: fp16 hi*hi + fp8 cross GEMM-bilinear -> logits ----
// rows r = s*32+b; A[m] = Enc[r-32] (rows r<32 garbage, fixed by kernel 2)
// C = A@W = hi*hi (fp16) + 2^-12 * (AL8@B8h + A8h@BL8)   (fp8 cross)
// logit[r] = sum_n C[r,n] * Enc[r,n] * hid[b,n]
//
// SMEM per buffer:
//   Ah16 128x40h (80B rows, 10240) | Bh16 10240 |
//   AL8 128x48B (6144) | AH8 6144 | B8H 6144 | B8L 6144   -> 45056
#define ST16      80
#define ST8       48
#define OFF_AH16  0
#define OFF_BH16  10240
#define OFF_AL8   20480
#define OFF_AH8   26624
#define OFF_B8H   32768
#define OFF_B8L   38912
#define BUF_B     45056
#define SMEM_TOTAL (2 * BUF_B)   // 90112

__global__ __launch_bounds__(256) void bilinear_hmma(
    const float* __restrict__ enc, const float* __restrict__ hid,
    float* __restrict__ logits)
{
    extern __shared__ char smem[];
    const uint32_t sb = smem_u32(smem);
    const int tid = threadIdx.x;
    const int lane = tid & 31, wid = tid >> 5;
    const int warp_m = wid >> 2;     // 0..1 : m offset 64*warp_m
    const int warp_n = wid & 3;      // 0..3 : n offset 32*warp_n
    const int m0 = blockIdx.x * 128;

    // ---- A fill mapping: rows rrow+32i, 4 fp32 at k=c4 ----
    const int rrow = tid >> 3;           // 0..31
    const int c4   = (tid & 7) * 4;      // 0,4,..,28
    const float* aptr[4];
    uint32_t a16sts[4], a8sts[4];
#pragma unroll
    for (int i = 0; i < 4; ++i) {
        const int row = rrow + i * 32;
        long gr = (long)m0 + row - B_DIM; if (gr < 0) gr = 0;
        aptr[i]   = enc + (size_t)gr * H_DIM + c4;
        a16sts[i] = (uint32_t)(OFF_AH16 + row * ST16 + c4 * 2);
        a8sts[i]  = (uint32_t)(row * ST8 + c4);          // add OFF_AL8/OFF_AH8
    }

    // ---- B cp.async mapping ----
    // Bh16: 512 chunks of 16B: idx = tid, tid+256 -> row idx>>2, ch idx&3
    const int b16r0 = tid >> 2,  b16c = (tid & 3);
    // B8:  256 chunks: row tid>>1, ch tid&1
    const int b8r = tid >> 1, b8c = tid & 1;

    // ---- ldmatrix addresses ----
    uint32_t ah_addr[4], a8_addr[4];
#pragma unroll
    for (int mt = 0; mt < 4; ++mt) {
        const int arow = warp_m * 64 + mt * 16 + (lane & 15);
        const int chnk = (lane >> 4) & 1;
        ah_addr[mt] = sb + (uint32_t)(OFF_AH16 + arow * ST16 + chnk * 16);
        a8_addr[mt] = sb + (uint32_t)(arow * ST8 + chnk * 16);   // add OFF_AL8/OFF_AH8
    }
    uint32_t bh_addr[2];
#pragma unroll
    for (int p = 0; p < 2; ++p)
        bh_addr[p] = sb + (uint32_t)(OFF_BH16 +
                     (warp_n * 32 + p * 16 + (lane & 15)) * ST16 + ((lane >> 4) & 1) * 16);
    uint32_t b8_addr[2];
#pragma unroll
    for (int p = 0; p < 2; ++p) {
        const int brow = warp_n * 32 + p * 16 + (lane & 7) + ((lane & 16) >> 1);
        const int chnk = (lane >> 3) & 1;
        b8_addr[p] = sb + (uint32_t)(brow * ST8 + chnk * 16);    // add OFF_B8H/OFF_B8L
    }

    float rowacc[4][2];
#pragma unroll
    for (int mt = 0; mt < 4; ++mt) { rowacc[mt][0] = 0.f; rowacc[mt][1] = 0.f; }

#pragma unroll 1
    for (int nt = 0; nt < 4; ++nt) {
        const int nbase = nt * 128;

        float chh[4][4][4];    // fp16 hi*hi accumulators
        float ccr[4][4][4];    // fp8 cross accumulators (scaled 2^12)
#pragma unroll
        for (int mt = 0; mt < 4; ++mt)
#pragma unroll
            for (int ntl = 0; ntl < 4; ++ntl)
#pragma unroll
                for (int q = 0; q < 4; ++q) { chh[mt][ntl][q] = 0.f; ccr[mt][ntl][q] = 0.f; }

        float4 av[4];

        auto ldA = [&](int stage) {
            const int kb = stage * 32;
#pragma unroll
            for (int i = 0; i < 4; ++i) av[i] = *(const float4*)(aptr[i] + kb);
        };
        auto cpB = [&](int stage, int buf) {
            const int kb = stage * 32;
            const uint32_t bb = sb + buf * (uint32_t)BUF_B;
            // Bh16 (bytes: row*1024 + kb*2 + ch*16)
            CP16(bb + OFF_BH16 + (uint32_t)(b16r0 * ST16 + b16c * 16),
                 (const char*)g_Bh + ((size_t)(nbase + b16r0) << 10) + kb * 2 + b16c * 16);
            CP16(bb + OFF_BH16 + (uint32_t)((b16r0 + 64) * ST16 + b16c * 16),
                 (const char*)g_Bh + ((size_t)(nbase + b16r0 + 64) << 10) + kb * 2 + b16c * 16);
            // B8H / B8L (bytes: row*512 + kb + ch*16)
            CP16(bb + OFF_B8H + (uint32_t)(b8r * ST8 + b8c * 16),
                 (const char*)g_B8h + ((size_t)(nbase + b8r) << 9) + kb + b8c * 16);
            CP16(bb + OFF_B8L + (uint32_t)(b8r * ST8 + b8c * 16),
                 (const char*)g_B8l + ((size_t)(nbase + b8r) << 9) + kb + b8c * 16);
            CP_COMMIT();
        };
        auto cvtStoreA = [&](int buf) {
            char* base = smem + buf * BUF_B;
#pragma unroll
            for (int i = 0; i < 4; ++i) {
                const float4 v = av[i];
                // fp16 hi split
                __half2 h01 = __floats2half2_rn(v.x, v.y);
                __half2 h23 = __floats2half2_rn(v.z, v.w);
                float2 f01 = __half22float2(h01);
                float2 f23 = __half22float2(h23);
                uint2 hw; hw.x = *(uint32_t*)&h01; hw.y = *(uint32_t*)&h23;
                *(uint2*)(base + a16sts[i]) = hw;
                // fp8 of hi
                uint32_t ah8 = (uint32_t)cvt8x2(f01.y, f01.x)
                             | ((uint32_t)cvt8x2(f23.y, f23.x) << 16);
                *(uint32_t*)(base + OFF_AH8 + a8sts[i]) = ah8;
                // fp8 of lo * 2^12
                uint32_t al8 = (uint32_t)cvt8x2((v.y - f01.y) * CROSS_SCALE,
                                                (v.x - f01.x) * CROSS_SCALE)
                             | ((uint32_t)cvt8x2((v.w - f23.y) * CROSS_SCALE,
                                                 (v.z - f23.x) * CROSS_SCALE) << 16);
                *(uint32_t*)(base + OFF_AL8 + a8sts[i]) = al8;
            }
        };

        // ---- prologue: stage 0 -> buf 0 ----
        ldA(0);
        cpB(0, 0);
        cvtStoreA(0);
        CP_WAIT0();
        __syncthreads();

#pragma unroll 1
        for (int st = 0; st < 16; ++st) {
            const int buf = st & 1;
            if (st < 15) { ldA(st + 1); cpB(st + 1, buf ^ 1); }

            const uint32_t bo = buf ? (uint32_t)BUF_B : 0u;

            // ---- fp16 hi*hi: 2 x k16 ----
#pragma unroll
            for (int kk = 0; kk < 2; ++kk) {
                const uint32_t koff = bo + kk * 32;
                uint32_t afh[4][4], bfh[4][2];
#pragma unroll
                for (int mt = 0; mt < 4; ++mt)
                    LDSM4(afh[mt][0], afh[mt][1], afh[mt][2], afh[mt][3], ah_addr[mt] + koff);
#pragma unroll
                for (int p = 0; p < 2; ++p) {
                    uint32_t r0, r1, r2, r3;
                    LDSM4(r0, r1, r2, r3, bh_addr[p] + koff);
                    bfh[2 * p][0] = r0;     bfh[2 * p][1] = r2;
                    bfh[2 * p + 1][0] = r1; bfh[2 * p + 1][1] = r3;
                }
#pragma unroll
                for (int mt = 0; mt < 4; ++mt)
#pragma unroll
                    for (int ntl = 0; ntl < 4; ++ntl)
                        MMA16816(chh[mt][ntl], afh[mt], bfh[ntl][0], bfh[ntl][1]);
            }

            // ---- fp8 cross: k32 per instruction ----
            {
                uint32_t a8[4][4], b8[4][2];
                // AL8 @ B8H
#pragma unroll
                for (int mt = 0; mt < 4; ++mt)
                    LDSM4(a8[mt][0], a8[mt][1], a8[mt][2], a8[mt][3],
                          a8_addr[mt] + bo + OFF_AL8);
#pragma unroll
                for (int p = 0; p < 2; ++p) {
                    uint32_t r0, r1, r2, r3;
                    LDSM4(r0, r1, r2, r3, b8_addr[p] + bo + OFF_B8H);
                    b8[2 * p][0] = r0;     b8[2 * p][1] = r1;
                    b8[2 * p + 1][0] = r2; b8[2 * p + 1][1] = r3;
                }
#pragma unroll
                for (int mt = 0; mt < 4; ++mt)
#pragma unroll
                    for (int ntl = 0; ntl < 4; ++ntl)
                        MMA8(ccr[mt][ntl], a8[mt], b8[ntl][0], b8[ntl][1]);
                // AH8 @ B8L
#pragma unroll
                for (int mt = 0; mt < 4; ++mt)
                    LDSM4(a8[mt][0], a8[mt][1], a8[mt][2], a8[mt][3],
                          a8_addr[mt] + bo + OFF_AH8);
#pragma unroll
                for (int p = 0; p < 2; ++p) {
                    uint32_t r0, r1, r2, r3;
                    LDSM4(r0, r1, r2, r3, b8_addr[p] + bo + OFF_B8L);
                    b8[2 * p][0] = r0;     b8[2 * p][1] = r1;
                    b8[2 * p + 1][0] = r2; b8[2 * p + 1][1] = r3;
                }
#pragma unroll
                for (int mt = 0; mt < 4; ++mt)
#pragma unroll
                    for (int ntl = 0; ntl < 4; ++ntl)
                        MMA8(ccr[mt][ntl], a8[mt], b8[ntl][0], b8[ntl][1]);
            }

            if (st < 15) { cvtStoreA(buf ^ 1); CP_WAIT0(); }
            __syncthreads();
        }

        // ---- fused epilogue: rowacc += (Chh + 2^-12 Ccr) .* (Enc .* hid) ----
#pragma unroll
        for (int mt = 0; mt < 4; ++mt) {
#pragma unroll
            for (int j = 0; j < 2; ++j) {
                const int r = m0 + warp_m * 64 + mt * 16 + (lane >> 2) + j * 8;
                const float* er = enc + (size_t)r * H_DIM;
                const float* hr = hid + (size_t)(r & 31) * H_DIM;
                float acc = 0.f;
#pragma unroll
                for (int ntl = 0; ntl < 4; ++ntl) {
                    const int col = nbase + warp_n * 32 + ntl * 8 + (lane & 3) * 2;
                    const float2 e = *(const float2*)(er + col);
                    const float2 h = *(const float2*)(hr + col);
                    const float c0 = chh[mt][ntl][j * 2 + 0] + INV_CROSS * ccr[mt][ntl][j * 2 + 0];
                    const float c1 = chh[mt][ntl][j * 2 + 1] + INV_CROSS * ccr[mt][ntl][j * 2 + 1];
                    acc = fmaf(c0, e.x * h.x, acc);
                    acc = fmaf(c1, e.y * h.y, acc);
                }
                rowacc[mt][j] += acc;
            }
        }
        __syncthreads();   // buffers reused by next nt prologue
    }

    // ---- reduce: quad lanes -> shared rows -> global ----
    float* srow = (float*)smem;
    if (tid < 128) srow[tid] = 0.f;
    __syncthreads();
#pragma unroll
    for (int mt = 0; mt < 4; ++mt)
#pragma unroll
        for (int j = 0; j < 2; ++j) {
            float v = rowacc[mt][j];
            v += __shfl_xor_sync(0xffffffffu, v, 1);
            v += __shfl_xor_sync(0xffffffffu, v, 2);
            if ((lane & 3) == 0)
                atomicAdd(&srow[warp_m * 64 + mt * 16 + (lane >> 2) + j * 8], v);
        }
    __syncthreads();
    if (tid < 128) {
        const int r = m0 + tid;
        logits[(r & 31) * S_LEN + (r >> 5)] = srow[tid];   // out[b*4096 + s]
    }
}

// ---------------- kernel 2: affect term + s==0 fixup + softmax ----------------
__global__ __launch_bounds__(256) void softmax_finalize(
    const float* __restrict__ enc, const float* __restrict__ hid,
    const float* __restrict__ emb, const float* __restrict__ aff,
    float* __restrict__ out)
{
    const int b = blockIdx.x;
    const int tid = threadIdx.x;
    const int lane = tid & 31, wid = tid >> 5;
    __shared__ float red[8][4];
    __shared__ float fin[4];
    __shared__ float rmax[8];
    __shared__ float rsum[8];

    float a0 = 0.f, a1 = 0.f, a2 = 0.f, e0 = 0.f;
    for (int h = tid; h < H_DIM; h += 256) {
        const float hv = hid[b * H_DIM + h];
        a0 += hv * aff[h * 3 + 0];
        a1 += hv * aff[h * 3 + 1];
        a2 += hv * aff[h * 3 + 2];
        e0 += hv * enc[b * H_DIM + h];
    }
#pragma unroll
    for (int m = 16; m; m >>= 1) {
        a0 += __shfl_xor_sync(~0u, a0, m);
        a1 += __shfl_xor_sync(~0u, a1, m);
        a2 += __shfl_xor_sync(~0u, a2, m);
        e0 += __shfl_xor_sync(~0u, e0, m);
    }
    if (lane == 0) { red[wid][0] = a0; red[wid][1] = a1; red[wid][2] = a2; red[wid][3] = e0; }
    __syncthreads();
    if (tid < 4) {
        float s = 0.f;
        for (int w = 0; w < 8; ++w) s += red[w][tid];
        fin[tid] = s;
    }
    __syncthreads();
    const float A0 = fin[0], A1 = fin[1], A2 = fin[2], E0 = fin[3];

    float l[16];
    float mx = -INFINITY;
#pragma unroll
    for (int it = 0; it < 16; ++it) {
        const int s = tid + it * 256;
        float v = (s == 0) ? E0 : out[b * S_LEN + s];
        const float* ep = emb + ((size_t)s * B_DIM + b) * 3;
        v += A0 * ep[0] + A1 * ep[1] + A2 * ep[2];
        l[it] = v;
        mx = fmaxf(mx, v);
    }
#pragma unroll
    for (int m = 16; m; m >>= 1) mx = fmaxf(mx, __shfl_xor_sync(~0u, mx, m));
    if (lane == 0) rmax[wid] = mx;
    __syncthreads();
    if (tid == 0) {
        float m2 = rmax[0];
        for (int w = 1; w < 8; ++w) m2 = fmaxf(m2, rmax[w]);
        rmax[0] = m2;
    }
    __syncthreads();
    const float MX = rmax[0];

    float sum = 0.f;
#pragma unroll
    for (int it = 0; it < 16; ++it) { l[it] = expf(l[it] - MX); sum += l[it]; }
#pragma unroll
    for (int m = 16; m; m >>= 1) sum += __shfl_xor_sync(~0u, sum, m);
    if (lane == 0) rsum[wid] = sum;
    __syncthreads();
    if (tid == 0) {
        float s2 = 0.f;
        for (int w = 0; w < 8; ++w) s2 += rsum[w];
        rsum[0] = s2;
    }
    __syncthreads();
    const float inv = 1.0f / rsum[0];
#pragma unroll
    for (int it = 0; it < 16; ++it)
        out[b * S_LEN + tid + it * 256] = l[it] * inv;
}

// ---------------- launch ----------------
extern "C" void kernel_launch(void* const* d_in, const int* in_sizes, int n_in,
                              void* d_out, int out_size) {
    const float *hid = nullptr, *enc = nullptr, *emb = nullptr, *Wm = nullptr, *aff = nullptr;
    for (int i = 0; i < n_in; ++i) {
        switch (in_sizes[i]) {
            case 16384:    hid = (const float*)d_in[i]; break;  // hidden [1,32,512]
            case 67108864: enc = (const float*)d_in[i]; break;  // encoder_outputs [4096,32,512]
            case 393216:   emb = (const float*)d_in[i]; break;  // embedding [4096,32,3]
            case 262144:   Wm  = (const float*)d_in[i]; break;  // bigram_matrix [512,512]
            case 1536:     aff = (const float*)d_in[i]; break;  // affect_matrix [512,3]
        }
    }
    float* out = (float*)d_out;  // [32,1,4096] fp32; logits scratch then softmax

    cudaFuncSetAttribute(bilinear_hmma,
                         cudaFuncAttributeMaxDynamicSharedMemorySize, SMEM_TOTAL);

    split_w<<<(H_DIM * H_DIM) / 256, 256>>>(Wm);
    bilinear_hmma<<<(S_LEN * B_DIM) / 128, 256, SMEM_TOTAL>>>(enc, hid, out);
    softmax_finalize<<<B_DIM, 256>>>(enc, hid, emb, aff, out);
}